// round 1
// baseline (speedup 1.0000x reference)
#include <cuda_runtime.h>
#include <cuda_fp16.h>
#include <cstdint>

// Problem dims (fixed by the dataset)
constexpr int TT = 4096;    // tokens (2*2048)
constexpr int KK = 4096;    // in_features
constexpr int II = 11008;   // intermediate
constexpr int OO = 4096;    // out_features

// GEMM tiling
constexpr int BM = 128;
constexpr int BN = 64;
constexpr int BK = 32;
constexpr int SA = 40;   // A smem row stride (halves), conflict-free for ldmatrix
constexpr int SB = 72;   // B smem row stride (halves), conflict-free for ldmatrix

// ---------------- device scratch (static allocation is allowed) ----------------
__device__ __half g_Wg[(size_t)KK * II];
__device__ __half g_Wu[(size_t)KK * II];
__device__ __half g_Wd[(size_t)II * OO];
__device__ __half g_X [(size_t)TT * KK];
__device__ __half g_H [(size_t)TT * II];

// ---------------- small helpers ----------------
__device__ __forceinline__ uint32_t cvt_smem(const void* p) {
    return (uint32_t)__cvta_generic_to_shared(p);
}

#define CP16(saddr, gptr) \
    asm volatile("cp.async.cg.shared.global [%0], [%1], 16;\n" :: "r"(saddr), "l"(gptr))

#define LDSM4(r, addr) \
    asm volatile("ldmatrix.sync.aligned.m8n8.x4.shared.b16 {%0,%1,%2,%3}, [%4];\n" \
        : "=r"((r)[0]), "=r"((r)[1]), "=r"((r)[2]), "=r"((r)[3]) : "r"(addr))

#define LDSM4T(r0, r1, r2, r3, addr) \
    asm volatile("ldmatrix.sync.aligned.m8n8.x4.trans.shared.b16 {%0,%1,%2,%3}, [%4];\n" \
        : "=r"(r0), "=r"(r1), "=r"(r2), "=r"(r3) : "r"(addr))

#define MMA16816(d, a, b) \
    asm volatile("mma.sync.aligned.m16n8k16.row.col.f32.f16.f16.f32 " \
        "{%0,%1,%2,%3}, {%4,%5,%6,%7}, {%8,%9}, {%0,%1,%2,%3};\n" \
        : "+f"((d)[0]), "+f"((d)[1]), "+f"((d)[2]), "+f"((d)[3]) \
        : "r"((a)[0]), "r"((a)[1]), "r"((a)[2]), "r"((a)[3]), "r"((b)[0]), "r"((b)[1]))

// ---------------- x fp32 -> fp16 ----------------
__global__ void f2h_kernel(const float* __restrict__ x) {
    size_t i = (size_t)blockIdx.x * blockDim.x + threadIdx.x;  // one float4 per thread
    float4 v = ((const float4*)x)[i];
    __half2* o = (__half2*)g_X;
    o[2 * i + 0] = __floats2half2_rn(v.x, v.y);
    o[2 * i + 1] = __floats2half2_rn(v.z, v.w);
}

// ---------------- AWQ int4 dequant -> fp16 row-major [rows, cols] ----------------
template <int WHICH>
__global__ void dequant_kernel(const int* __restrict__ qw, const float* __restrict__ sc,
                               const int* __restrict__ qz, int rows, int cols) {
    __half* W = (WHICH == 0) ? g_Wg : (WHICH == 1) ? g_Wu : g_Wd;
    const int wpr = cols >> 3;  // int32 words per row
    size_t idx = (size_t)blockIdx.x * blockDim.x + threadIdx.x;
    if (idx >= (size_t)rows * wpr) return;
    int j = (int)(idx % wpr);
    int k = (int)(idx / wpr);
    int grp = k >> 7;  // GROUP = 128

    unsigned w = ((const unsigned*)qw)[idx];
    unsigned z = ((const unsigned*)qz)[(size_t)grp * wpr + j];
    const float* srow = sc + (size_t)grp * cols + j * 8;
    float4 s0 = *(const float4*)(srow);
    float4 s1 = *(const float4*)(srow + 4);

    __half2 h[4];
    h[0] = __floats2half2_rn((float)((int)(w & 0xF)         - (int)(z & 0xF))         * s0.x,
                             (float)((int)((w >> 4) & 0xF)  - (int)((z >> 4) & 0xF))  * s0.y);
    h[1] = __floats2half2_rn((float)((int)((w >> 8) & 0xF)  - (int)((z >> 8) & 0xF))  * s0.z,
                             (float)((int)((w >> 12) & 0xF) - (int)((z >> 12) & 0xF)) * s0.w);
    h[2] = __floats2half2_rn((float)((int)((w >> 16) & 0xF) - (int)((z >> 16) & 0xF)) * s1.x,
                             (float)((int)((w >> 20) & 0xF) - (int)((z >> 20) & 0xF)) * s1.y);
    h[3] = __floats2half2_rn((float)((int)((w >> 24) & 0xF) - (int)((z >> 24) & 0xF)) * s1.z,
                             (float)((int)((w >> 28) & 0xF) - (int)((z >> 28) & 0xF)) * s1.w);

    *(uint4*)(W + (size_t)k * cols + j * 8) = *(uint4*)h;
}

// ---------------- GEMM1: H = silu(X @ Wg) * (X @ Wu), fp16 out ----------------
__global__ __launch_bounds__(256, 1) void gemm_gateup_kernel() {
    __shared__ __half As [2][BM * SA];
    __shared__ __half Bgs[2][BK * SB];
    __shared__ __half Bus[2][BK * SB];

    const int tid  = threadIdx.x;
    const int lane = tid & 31;
    const int warp = tid >> 5;
    const int wm   = warp & 3;   // 4 warps along M
    const int wn   = warp >> 2;  // 2 warps along N
    const int m0   = blockIdx.y * BM;
    const int n0   = blockIdx.x * BN;

    const int arow = tid >> 2;           // A: 128 rows x 4 uint4/row; 2 chunks/thread
    const int acol = (tid & 3) << 3;
    const int brow = tid >> 3;           // B: 32 rows x 8 uint4/row; 1 chunk/thread
    const int bcol = (tid & 7) << 3;

    const __half* gA  = g_X  + (size_t)(m0 + arow) * KK + acol;
    const __half* gBg = g_Wg + (size_t)brow * II + n0 + bcol;
    const __half* gBu = g_Wu + (size_t)brow * II + n0 + bcol;

    float cg[2][4][4];
    float cu[2][4][4];
#pragma unroll
    for (int i = 0; i < 2; i++)
#pragma unroll
        for (int j = 0; j < 4; j++)
#pragma unroll
            for (int l = 0; l < 4; l++) { cg[i][j][l] = 0.f; cu[i][j][l] = 0.f; }

#define LOAD_GU(buf, k0) do {                                                          \
        CP16(cvt_smem(&As[buf][arow * SA + acol]), gA + (k0));                          \
        CP16(cvt_smem(&As[buf][(arow + 64) * SA + acol]), gA + (size_t)64 * KK + (k0)); \
        CP16(cvt_smem(&Bgs[buf][brow * SB + bcol]), gBg + (size_t)(k0) * II);           \
        CP16(cvt_smem(&Bus[buf][brow * SB + bcol]), gBu + (size_t)(k0) * II);           \
        asm volatile("cp.async.commit_group;\n");                                      \
    } while (0)

    constexpr int KT = KK / BK;  // 128
    LOAD_GU(0, 0);
    int buf = 0;
    for (int kt = 0; kt < KT; ++kt) {
        if (kt + 1 < KT) {
            LOAD_GU(buf ^ 1, (kt + 1) * BK);
            asm volatile("cp.async.wait_group 1;\n");
        } else {
            asm volatile("cp.async.wait_group 0;\n");
        }
        __syncthreads();

#pragma unroll
        for (int ks = 0; ks < 2; ++ks) {
            uint32_t a[2][4];
#pragma unroll
            for (int mi = 0; mi < 2; ++mi) {
                uint32_t addr = cvt_smem(&As[buf][(wm * 32 + mi * 16 + (lane & 15)) * SA +
                                                  ks * 16 + (lane >> 4) * 8]);
                LDSM4(a[mi], addr);
            }
            uint32_t bg[4][2], bu[4][2];
#pragma unroll
            for (int nh = 0; nh < 2; ++nh) {
                uint32_t ag = cvt_smem(&Bgs[buf][(ks * 16 + (lane & 15)) * SB +
                                                 wn * 32 + nh * 16 + (lane >> 4) * 8]);
                LDSM4T(bg[nh * 2][0], bg[nh * 2][1], bg[nh * 2 + 1][0], bg[nh * 2 + 1][1], ag);
                uint32_t au = cvt_smem(&Bus[buf][(ks * 16 + (lane & 15)) * SB +
                                                 wn * 32 + nh * 16 + (lane >> 4) * 8]);
                LDSM4T(bu[nh * 2][0], bu[nh * 2][1], bu[nh * 2 + 1][0], bu[nh * 2 + 1][1], au);
            }
#pragma unroll
            for (int mi = 0; mi < 2; ++mi)
#pragma unroll
                for (int nj = 0; nj < 4; ++nj) {
                    MMA16816(cg[mi][nj], a[mi], bg[nj]);
                    MMA16816(cu[mi][nj], a[mi], bu[nj]);
                }
        }
        __syncthreads();
        buf ^= 1;
    }

    // epilogue: h = silu(g) * u, fp16
#pragma unroll
    for (int mi = 0; mi < 2; ++mi)
#pragma unroll
        for (int nj = 0; nj < 4; ++nj) {
            int r = m0 + wm * 32 + mi * 16 + (lane >> 2);
            int c = n0 + wn * 32 + nj * 8 + (lane & 3) * 2;
            float g0 = cg[mi][nj][0], g1 = cg[mi][nj][1];
            float g2 = cg[mi][nj][2], g3 = cg[mi][nj][3];
            float u0 = cu[mi][nj][0], u1 = cu[mi][nj][1];
            float u2 = cu[mi][nj][2], u3 = cu[mi][nj][3];
            float h0 = g0 / (1.f + __expf(-g0)) * u0;
            float h1 = g1 / (1.f + __expf(-g1)) * u1;
            float h2 = g2 / (1.f + __expf(-g2)) * u2;
            float h3 = g3 / (1.f + __expf(-g3)) * u3;
            *(__half2*)(g_H + (size_t)r * II + c)       = __floats2half2_rn(h0, h1);
            *(__half2*)(g_H + (size_t)(r + 8) * II + c) = __floats2half2_rn(h2, h3);
        }
}

// ---------------- GEMM2: out = H @ Wd, fp32 out ----------------
__global__ __launch_bounds__(256, 1) void gemm_down_kernel(float* __restrict__ out) {
    __shared__ __half As[2][BM * SA];
    __shared__ __half Bs[2][BK * SB];

    const int tid  = threadIdx.x;
    const int lane = tid & 31;
    const int warp = tid >> 5;
    const int wm   = warp & 3;
    const int wn   = warp >> 2;
    const int m0   = blockIdx.y * BM;
    const int n0   = blockIdx.x * BN;

    const int arow = tid >> 2;
    const int acol = (tid & 3) << 3;
    const int brow = tid >> 3;
    const int bcol = (tid & 7) << 3;

    const __half* gA = g_H  + (size_t)(m0 + arow) * II + acol;
    const __half* gB = g_Wd + (size_t)brow * OO + n0 + bcol;

    float cc[2][4][4];
#pragma unroll
    for (int i = 0; i < 2; i++)
#pragma unroll
        for (int j = 0; j < 4; j++)
#pragma unroll
            for (int l = 0; l < 4; l++) cc[i][j][l] = 0.f;

#define LOAD_D(buf, k0) do {                                                           \
        CP16(cvt_smem(&As[buf][arow * SA + acol]), gA + (k0));                          \
        CP16(cvt_smem(&As[buf][(arow + 64) * SA + acol]), gA + (size_t)64 * II + (k0)); \
        CP16(cvt_smem(&Bs[buf][brow * SB + bcol]), gB + (size_t)(k0) * OO);             \
        asm volatile("cp.async.commit_group;\n");                                      \
    } while (0)

    constexpr int KT = II / BK;  // 344
    LOAD_D(0, 0);
    int buf = 0;
    for (int kt = 0; kt < KT; ++kt) {
        if (kt + 1 < KT) {
            LOAD_D(buf ^ 1, (kt + 1) * BK);
            asm volatile("cp.async.wait_group 1;\n");
        } else {
            asm volatile("cp.async.wait_group 0;\n");
        }
        __syncthreads();

#pragma unroll
        for (int ks = 0; ks < 2; ++ks) {
            uint32_t a[2][4];
#pragma unroll
            for (int mi = 0; mi < 2; ++mi) {
                uint32_t addr = cvt_smem(&As[buf][(wm * 32 + mi * 16 + (lane & 15)) * SA +
                                                  ks * 16 + (lane >> 4) * 8]);
                LDSM4(a[mi], addr);
            }
            uint32_t b[4][2];
#pragma unroll
            for (int nh = 0; nh < 2; ++nh) {
                uint32_t ab = cvt_smem(&Bs[buf][(ks * 16 + (lane & 15)) * SB +
                                                wn * 32 + nh * 16 + (lane >> 4) * 8]);
                LDSM4T(b[nh * 2][0], b[nh * 2][1], b[nh * 2 + 1][0], b[nh * 2 + 1][1], ab);
            }
#pragma unroll
            for (int mi = 0; mi < 2; ++mi)
#pragma unroll
                for (int nj = 0; nj < 4; ++nj) MMA16816(cc[mi][nj], a[mi], b[nj]);
        }
        __syncthreads();
        buf ^= 1;
    }

#pragma unroll
    for (int mi = 0; mi < 2; ++mi)
#pragma unroll
        for (int nj = 0; nj < 4; ++nj) {
            int r = m0 + wm * 32 + mi * 16 + (lane >> 2);
            int c = n0 + wn * 32 + nj * 8 + (lane & 3) * 2;
            float2 v0 = make_float2(cc[mi][nj][0], cc[mi][nj][1]);
            float2 v1 = make_float2(cc[mi][nj][2], cc[mi][nj][3]);
            *(float2*)(out + (size_t)r * OO + c)       = v0;
            *(float2*)(out + (size_t)(r + 8) * OO + c) = v1;
        }
}

// ---------------- launch ----------------
extern "C" void kernel_launch(void* const* d_in, const int* in_sizes, int n_in,
                              void* d_out, int out_size) {
    (void)in_sizes; (void)n_in; (void)out_size;
    const float* x   = (const float*)d_in[0];
    const int*   gqw = (const int*)d_in[1];
    const float* gsc = (const float*)d_in[2];
    const int*   gqz = (const int*)d_in[3];
    const int*   uqw = (const int*)d_in[4];
    const float* usc = (const float*)d_in[5];
    const int*   uqz = (const int*)d_in[6];
    const int*   dqw = (const int*)d_in[7];
    const float* dsc = (const float*)d_in[8];
    const int*   dqz = (const int*)d_in[9];
    float* out = (float*)d_out;

    // x -> fp16
    f2h_kernel<<<(TT * KK / 4) / 256, 256>>>(x);

    // dequant all three weight matrices
    int words1 = KK * (II / 8);
    dequant_kernel<0><<<(words1 + 255) / 256, 256>>>(gqw, gsc, gqz, KK, II);
    dequant_kernel<1><<<(words1 + 255) / 256, 256>>>(uqw, usc, uqz, KK, II);
    int words2 = II * (OO / 8);
    dequant_kernel<2><<<(words2 + 255) / 256, 256>>>(dqw, dsc, dqz, II, OO);

    // fused gate/up GEMM + silu*mul
    gemm_gateup_kernel<<<dim3(II / BN, TT / BM), 256>>>();

    // down GEMM
    gemm_down_kernel<<<dim3(OO / BN, TT / BM), 256>>>(out);
}

// round 3
// speedup vs baseline: 1.2451x; 1.2451x over previous
#include <cuda_runtime.h>
#include <cuda_fp16.h>
#include <cstdint>

// Problem dims (fixed by the dataset)
constexpr int TT = 4096;    // tokens
constexpr int KK = 4096;    // in_features
constexpr int II = 11008;   // intermediate
constexpr int OO = 4096;    // out_features

constexpr int BK = 32;      // k per stage
constexpr int NS = 4;       // pipeline stages
constexpr int SA = 40;      // A smem row stride (halves)
constexpr int SB = 72;      // B smem row stride (halves), BN=64
constexpr int SBD = 136;    // B smem row stride (halves), BN=128

// ---------------- device scratch ----------------
__device__ __align__(256) __half g_Wg[(size_t)KK * II];
__device__ __align__(256) __half g_Wu[(size_t)KK * II];
__device__ __align__(256) __half g_Wd[(size_t)II * OO];
__device__ __align__(256) __half g_X [(size_t)TT * KK];
__device__ __align__(256) __half g_H [(size_t)TT * II];

// ---------------- helpers ----------------
__device__ __forceinline__ uint32_t cvt_smem(const void* p) {
    return (uint32_t)__cvta_generic_to_shared(p);
}

#define CP16(saddr, gptr) \
    asm volatile("cp.async.cg.shared.global [%0], [%1], 16;\n" :: "r"(saddr), "l"(gptr))

#define CP_COMMIT() asm volatile("cp.async.commit_group;\n")
#define CP_WAIT2()  asm volatile("cp.async.wait_group 2;\n")

#define LDSM4(r, addr) \
    asm volatile("ldmatrix.sync.aligned.m8n8.x4.shared.b16 {%0,%1,%2,%3}, [%4];\n" \
        : "=r"((r)[0]), "=r"((r)[1]), "=r"((r)[2]), "=r"((r)[3]) : "r"(addr))

#define LDSM4T(r0, r1, r2, r3, addr) \
    asm volatile("ldmatrix.sync.aligned.m8n8.x4.trans.shared.b16 {%0,%1,%2,%3}, [%4];\n" \
        : "=r"(r0), "=r"(r1), "=r"(r2), "=r"(r3) : "r"(addr))

#define MMA16816(d, a, b) \
    asm volatile("mma.sync.aligned.m16n8k16.row.col.f32.f16.f16.f32 " \
        "{%0,%1,%2,%3}, {%4,%5,%6,%7}, {%8,%9}, {%0,%1,%2,%3};\n" \
        : "+f"((d)[0]), "+f"((d)[1]), "+f"((d)[2]), "+f"((d)[3]) \
        : "r"((a)[0]), "r"((a)[1]), "r"((a)[2]), "r"((a)[3]), "r"((b)[0]), "r"((b)[1]))

// ---------------- x fp32 -> fp16 ----------------
__global__ void f2h_kernel(const float* __restrict__ x) {
    size_t i = (size_t)blockIdx.x * blockDim.x + threadIdx.x;
    float4 v = ((const float4*)x)[i];
    __half2* o = (__half2*)g_X;
    o[2 * i + 0] = __floats2half2_rn(v.x, v.y);
    o[2 * i + 1] = __floats2half2_rn(v.z, v.w);
}

// ---------------- AWQ int4 dequant -> fp16 row-major [rows, cols] ----------------
template <int WHICH>
__global__ void dequant_kernel(const int* __restrict__ qw, const float* __restrict__ sc,
                               const int* __restrict__ qz, int rows, int cols) {
    __half* W = (WHICH == 0) ? g_Wg : (WHICH == 1) ? g_Wu : g_Wd;
    const int wpr = cols >> 3;
    size_t idx = (size_t)blockIdx.x * blockDim.x + threadIdx.x;
    if (idx >= (size_t)rows * wpr) return;
    int j = (int)(idx % wpr);
    int k = (int)(idx / wpr);
    int grp = k >> 7;

    unsigned w = ((const unsigned*)qw)[idx];
    unsigned z = ((const unsigned*)qz)[(size_t)grp * wpr + j];
    const float* srow = sc + (size_t)grp * cols + j * 8;
    float4 s0 = *(const float4*)(srow);
    float4 s1 = *(const float4*)(srow + 4);

    __half2 h[4];
    h[0] = __floats2half2_rn((float)((int)(w & 0xF)         - (int)(z & 0xF))         * s0.x,
                             (float)((int)((w >> 4) & 0xF)  - (int)((z >> 4) & 0xF))  * s0.y);
    h[1] = __floats2half2_rn((float)((int)((w >> 8) & 0xF)  - (int)((z >> 8) & 0xF))  * s0.z,
                             (float)((int)((w >> 12) & 0xF) - (int)((z >> 12) & 0xF)) * s0.w);
    h[2] = __floats2half2_rn((float)((int)((w >> 16) & 0xF) - (int)((z >> 16) & 0xF)) * s1.x,
                             (float)((int)((w >> 20) & 0xF) - (int)((z >> 20) & 0xF)) * s1.y);
    h[3] = __floats2half2_rn((float)((int)((w >> 24) & 0xF) - (int)((z >> 24) & 0xF)) * s1.z,
                             (float)((int)((w >> 28) & 0xF) - (int)((z >> 28) & 0xF)) * s1.w);

    *(uint4*)(W + (size_t)k * cols + j * 8) = *(uint4*)h;
}

// ============================================================================
// GEMM1 (fused gate+up): BM=256, N=64 gate + 64 up, BK=32, 512 threads.
// 16 warps = 4(m) x 4(n). Warp tile: 64 rows x (16 gate cols + 16 up cols).
// ============================================================================
constexpr int GU_A_HALVES = 256 * SA;          // 10240
constexpr int GU_B_HALVES = 32 * SB;           // 2304
constexpr int GU_STAGE_HALVES = GU_A_HALVES + 2 * GU_B_HALVES;  // 14848
constexpr int GU_SMEM_BYTES = NS * GU_STAGE_HALVES * 2;         // 118784

__global__ __launch_bounds__(512, 1) void gemm_gateup() {
    extern __shared__ __half sm[];

    const int tid  = threadIdx.x;
    const int lane = tid & 31;
    const int warp = tid >> 5;
    const int wm   = warp & 3;   // 4 warps along M (64 rows each)
    const int wn   = warp >> 2;  // 4 warps along N (16 cols each)
    const int m0   = blockIdx.x * 256;
    const int n0   = blockIdx.y * 64;

    // cp.async mapping
    const int arow = tid >> 2;            // 0..127 (two rows per thread: +0, +128)
    const int acol = (tid & 3) << 3;
    const int brow = (tid & 255) >> 3;    // 0..31
    const int bcol = (tid & 7) << 3;
    const bool isBg = tid < 256;          // threads 0-255 -> Bg, 256-511 -> Bu

    const __half* gA = g_X + (size_t)(m0 + arow) * KK + acol;
    const __half* gB = (isBg ? g_Wg : g_Wu) + (size_t)brow * II + n0 + bcol;

    float cg[4][2][4];
    float cu[4][2][4];
#pragma unroll
    for (int i = 0; i < 4; i++)
#pragma unroll
        for (int j = 0; j < 2; j++)
#pragma unroll
            for (int l = 0; l < 4; l++) { cg[i][j][l] = 0.f; cu[i][j][l] = 0.f; }

#define GU_LOAD(stg) do {                                                              \
        const int _slot = (stg) % NS;                                                  \
        __half* _s = sm + _slot * GU_STAGE_HALVES;                                     \
        const int _k0 = (stg) * BK;                                                    \
        CP16(cvt_smem(_s + arow * SA + acol), gA + _k0);                               \
        CP16(cvt_smem(_s + (arow + 128) * SA + acol), gA + (size_t)128 * KK + _k0);    \
        __half* _b = _s + GU_A_HALVES + (isBg ? 0 : GU_B_HALVES);                      \
        CP16(cvt_smem(_b + brow * SB + bcol), gB + (size_t)_k0 * II);                  \
        CP_COMMIT();                                                                   \
    } while (0)

    constexpr int KT = KK / BK;  // 128
#pragma unroll
    for (int p = 0; p < NS - 1; ++p) GU_LOAD(p);

    for (int kt = 0; kt < KT; ++kt) {
        CP_WAIT2();
        __syncthreads();
        if (kt + NS - 1 < KT) GU_LOAD(kt + NS - 1);
        else CP_COMMIT();

        __half* s = sm + (kt % NS) * GU_STAGE_HALVES;
        __half* sBg = s + GU_A_HALVES;
        __half* sBu = sBg + GU_B_HALVES;

#pragma unroll
        for (int ks = 0; ks < 2; ++ks) {
            uint32_t a[4][4];
#pragma unroll
            for (int mi = 0; mi < 4; ++mi) {
                uint32_t addr = cvt_smem(s + (wm * 64 + mi * 16 + (lane & 15)) * SA +
                                         ks * 16 + (lane >> 4) * 8);
                LDSM4(a[mi], addr);
            }
            uint32_t bg[2][2], bu[2][2];
            {
                uint32_t ag = cvt_smem(sBg + (ks * 16 + (lane & 15)) * SB +
                                       wn * 16 + (lane >> 4) * 8);
                LDSM4T(bg[0][0], bg[0][1], bg[1][0], bg[1][1], ag);
                uint32_t au = cvt_smem(sBu + (ks * 16 + (lane & 15)) * SB +
                                       wn * 16 + (lane >> 4) * 8);
                LDSM4T(bu[0][0], bu[0][1], bu[1][0], bu[1][1], au);
            }
#pragma unroll
            for (int mi = 0; mi < 4; ++mi)
#pragma unroll
                for (int nj = 0; nj < 2; ++nj) {
                    MMA16816(cg[mi][nj], a[mi], bg[nj]);
                    MMA16816(cu[mi][nj], a[mi], bu[nj]);
                }
        }
    }

    // epilogue: h = silu(g) * u  (warp-local; gate/up cols match)
#pragma unroll
    for (int mi = 0; mi < 4; ++mi)
#pragma unroll
        for (int nj = 0; nj < 2; ++nj) {
            int r = m0 + wm * 64 + mi * 16 + (lane >> 2);
            int c = n0 + wn * 16 + nj * 8 + (lane & 3) * 2;
            float g0 = cg[mi][nj][0], g1 = cg[mi][nj][1];
            float g2 = cg[mi][nj][2], g3 = cg[mi][nj][3];
            float u0 = cu[mi][nj][0], u1 = cu[mi][nj][1];
            float u2 = cu[mi][nj][2], u3 = cu[mi][nj][3];
            float h0 = g0 / (1.f + __expf(-g0)) * u0;
            float h1 = g1 / (1.f + __expf(-g1)) * u1;
            float h2 = g2 / (1.f + __expf(-g2)) * u2;
            float h3 = g3 / (1.f + __expf(-g3)) * u3;
            *(__half2*)(g_H + (size_t)r * II + c)       = __floats2half2_rn(h0, h1);
            *(__half2*)(g_H + (size_t)(r + 8) * II + c) = __floats2half2_rn(h2, h3);
        }
}

// ============================================================================
// GEMM2 (down): BM=256, BN=128, BK=32, 512 threads.
// 16 warps = 4(m) x 4(n). Warp tile: 64 x 32.
// ============================================================================
constexpr int DN_A_HALVES = 256 * SA;               // 10240
constexpr int DN_B_HALVES = 32 * SBD;               // 4352
constexpr int DN_STAGE_HALVES = DN_A_HALVES + DN_B_HALVES;  // 14592
constexpr int DN_SMEM_BYTES = NS * DN_STAGE_HALVES * 2;     // 116736

__global__ __launch_bounds__(512, 1) void gemm_down(float* __restrict__ out) {
    extern __shared__ __half sm[];

    const int tid  = threadIdx.x;
    const int lane = tid & 31;
    const int warp = tid >> 5;
    const int wm   = warp & 3;
    const int wn   = warp >> 2;
    const int m0   = blockIdx.x * 256;
    const int n0   = blockIdx.y * 128;

    const int arow = tid >> 2;            // 0..127 (+0, +128)
    const int acol = (tid & 3) << 3;
    const int brow = tid >> 4;            // 0..31
    const int bcol = (tid & 15) << 3;

    const __half* gA = g_H  + (size_t)(m0 + arow) * II + acol;
    const __half* gB = g_Wd + (size_t)brow * OO + n0 + bcol;

    float cc[4][4][4];
#pragma unroll
    for (int i = 0; i < 4; i++)
#pragma unroll
        for (int j = 0; j < 4; j++)
#pragma unroll
            for (int l = 0; l < 4; l++) cc[i][j][l] = 0.f;

#define DN_LOAD(stg) do {                                                              \
        const int _slot = (stg) % NS;                                                  \
        __half* _s = sm + _slot * DN_STAGE_HALVES;                                     \
        const int _k0 = (stg) * BK;                                                    \
        CP16(cvt_smem(_s + arow * SA + acol), gA + _k0);                               \
        CP16(cvt_smem(_s + (arow + 128) * SA + acol), gA + (size_t)128 * II + _k0);    \
        CP16(cvt_smem(_s + DN_A_HALVES + brow * SBD + bcol), gB + (size_t)_k0 * OO);   \
        CP_COMMIT();                                                                   \
    } while (0)

    constexpr int KT = II / BK;  // 344
#pragma unroll
    for (int p = 0; p < NS - 1; ++p) DN_LOAD(p);

    for (int kt = 0; kt < KT; ++kt) {
        CP_WAIT2();
        __syncthreads();
        if (kt + NS - 1 < KT) DN_LOAD(kt + NS - 1);
        else CP_COMMIT();

        __half* s = sm + (kt % NS) * DN_STAGE_HALVES;
        __half* sB = s + DN_A_HALVES;

#pragma unroll
        for (int ks = 0; ks < 2; ++ks) {
            uint32_t a[4][4];
#pragma unroll
            for (int mi = 0; mi < 4; ++mi) {
                uint32_t addr = cvt_smem(s + (wm * 64 + mi * 16 + (lane & 15)) * SA +
                                         ks * 16 + (lane >> 4) * 8);
                LDSM4(a[mi], addr);
            }
            uint32_t b[4][2];
#pragma unroll
            for (int nh = 0; nh < 2; ++nh) {
                uint32_t ab = cvt_smem(sB + (ks * 16 + (lane & 15)) * SBD +
                                       wn * 32 + nh * 16 + (lane >> 4) * 8);
                LDSM4T(b[nh * 2][0], b[nh * 2][1], b[nh * 2 + 1][0], b[nh * 2 + 1][1], ab);
            }
#pragma unroll
            for (int mi = 0; mi < 4; ++mi)
#pragma unroll
                for (int nj = 0; nj < 4; ++nj) MMA16816(cc[mi][nj], a[mi], b[nj]);
        }
    }

#pragma unroll
    for (int mi = 0; mi < 4; ++mi)
#pragma unroll
        for (int nj = 0; nj < 4; ++nj) {
            int r = m0 + wm * 64 + mi * 16 + (lane >> 2);
            int c = n0 + wn * 32 + nj * 8 + (lane & 3) * 2;
            *(float2*)(out + (size_t)r * OO + c)       = make_float2(cc[mi][nj][0], cc[mi][nj][1]);
            *(float2*)(out + (size_t)(r + 8) * OO + c) = make_float2(cc[mi][nj][2], cc[mi][nj][3]);
        }
}

// ---------------- launch ----------------
extern "C" void kernel_launch(void* const* d_in, const int* in_sizes, int n_in,
                              void* d_out, int out_size) {
    (void)in_sizes; (void)n_in; (void)out_size;
    const float* x   = (const float*)d_in[0];
    const int*   gqw = (const int*)d_in[1];
    const float* gsc = (const float*)d_in[2];
    const int*   gqz = (const int*)d_in[3];
    const int*   uqw = (const int*)d_in[4];
    const float* usc = (const float*)d_in[5];
    const int*   uqz = (const int*)d_in[6];
    const int*   dqw = (const int*)d_in[7];
    const float* dsc = (const float*)d_in[8];
    const int*   dqz = (const int*)d_in[9];
    float* out = (float*)d_out;

    // x -> fp16
    f2h_kernel<<<(TT * KK / 4) / 256, 256>>>(x);

    // dequant weights
    int words1 = KK * (II / 8);
    dequant_kernel<0><<<(words1 + 255) / 256, 256>>>(gqw, gsc, gqz, KK, II);
    dequant_kernel<1><<<(words1 + 255) / 256, 256>>>(uqw, usc, uqz, KK, II);
    int words2 = II * (OO / 8);
    dequant_kernel<2><<<(words2 + 255) / 256, 256>>>(dqw, dsc, dqz, II, OO);

    // fused gate/up GEMM + silu*mul
    cudaFuncSetAttribute(gemm_gateup, cudaFuncAttributeMaxDynamicSharedMemorySize, GU_SMEM_BYTES);
    gemm_gateup<<<dim3(TT / 256, II / 64), 512, GU_SMEM_BYTES>>>();

    // down GEMM
    cudaFuncSetAttribute(gemm_down, cudaFuncAttributeMaxDynamicSharedMemorySize, DN_SMEM_BYTES);
    gemm_down<<<dim3(TT / 256, OO / 128), 512, DN_SMEM_BYTES>>>(out);
}

// round 4
// speedup vs baseline: 1.9684x; 1.5810x over previous
#include <cuda_runtime.h>
#include <cuda_fp16.h>
#include <cuda.h>
#include <cstdint>

// Problem dims (fixed by the dataset)
constexpr int TT = 4096;    // tokens
constexpr int KK = 4096;    // in_features
constexpr int II = 11008;   // intermediate
constexpr int OO = 4096;    // out_features

constexpr int NS = 4;                    // pipeline stages
constexpr uint32_t GU_STAGE = 49152;     // A 32K | Bg 8K | Bu 8K
constexpr uint32_t DN_STAGE = 49152;     // A 32K | B0 8K | B1 8K
constexpr int SMEM_BYTES = 1024 + NS * 49152;  // 197632

// ---------------- device scratch ----------------
__device__ __align__(256) __half g_Wg[(size_t)KK * II];
__device__ __align__(256) __half g_Wu[(size_t)KK * II];
__device__ __align__(256) __half g_Wd[(size_t)II * OO];
__device__ __align__(256) __half g_X [(size_t)TT * KK];
__device__ __align__(256) __half g_H [(size_t)TT * II];

// ---------------- PTX helpers ----------------
__device__ __forceinline__ uint32_t smem_u32(const void* p) {
    return (uint32_t)__cvta_generic_to_shared(p);
}

#define MBAR_INIT(addr, cnt) \
    asm volatile("mbarrier.init.shared.b64 [%0], %1;" :: "r"(addr), "r"(cnt) : "memory")

#define MBAR_EXPECT_TX(addr, bytes) \
    asm volatile("mbarrier.arrive.expect_tx.shared.b64 _, [%0], %1;" :: "r"(addr), "r"(bytes) : "memory")

#define MBAR_ARRIVE(addr) \
    asm volatile("mbarrier.arrive.shared.b64 _, [%0];" :: "r"(addr) : "memory")

#define MBAR_WAIT(addr, par) do {                                                       \
    uint32_t _m = (addr); uint32_t _p = (par); uint32_t _d;                             \
    asm volatile("{\n .reg .pred p;\n"                                                  \
        " mbarrier.try_wait.parity.acquire.cta.shared::cta.b64 p, [%1], %2;\n"          \
        " selp.b32 %0, 1, 0, p;\n}"                                                     \
        : "=r"(_d) : "r"(_m), "r"(_p) : "memory");                                      \
    if (!_d) {                                                                          \
        asm volatile("{\n .reg .pred P1;\n"                                             \
            "WL_%=:\n"                                                                  \
            " mbarrier.try_wait.parity.acquire.cta.shared::cta.b64 P1, [%0], %1, 0x989680;\n" \
            " @P1 bra.uni WD_%=;\n bra.uni WL_%=;\nWD_%=:\n}"                           \
            :: "r"(_m), "r"(_p) : "memory");                                            \
    }                                                                                   \
} while (0)

#define MBAR_WAIT_RLX(addr, par) do {                                                   \
    uint32_t _m = (addr); uint32_t _p = (par); uint32_t _d;                             \
    asm volatile("{\n .reg .pred p;\n"                                                  \
        " mbarrier.try_wait.parity.relaxed.cta.shared::cta.b64 p, [%1], %2, 0x989680;\n"\
        " selp.b32 %0, 1, 0, p;\n}"                                                     \
        : "=r"(_d) : "r"(_m), "r"(_p) : "memory");                                      \
    if (!_d) {                                                                          \
        asm volatile("{\n .reg .pred P1;\n"                                             \
            "WL_%=:\n"                                                                  \
            " mbarrier.try_wait.parity.relaxed.cta.shared::cta.b64 P1, [%0], %1, 0x989680;\n" \
            " @P1 bra.uni WD_%=;\n bra.uni WL_%=;\nWD_%=:\n}"                           \
            :: "r"(_m), "r"(_p) : "memory");                                            \
    }                                                                                   \
} while (0)

#define TMA2D(dst, map, c0, c1, bar) \
    asm volatile("cp.async.bulk.tensor.2d.shared::cta.global.tile.mbarrier::complete_tx::bytes " \
                 "[%0], [%1, {%2, %3}], [%4];" \
                 :: "r"(dst), "l"(map), "r"(c0), "r"(c1), "r"(bar) : "memory")

#define LDSM4(r, addr) \
    asm volatile("ldmatrix.sync.aligned.m8n8.x4.shared.b16 {%0,%1,%2,%3}, [%4];\n" \
        : "=r"((r)[0]), "=r"((r)[1]), "=r"((r)[2]), "=r"((r)[3]) : "r"(addr))

#define LDSM4T(r0, r1, r2, r3, addr) \
    asm volatile("ldmatrix.sync.aligned.m8n8.x4.trans.shared.b16 {%0,%1,%2,%3}, [%4];\n" \
        : "=r"(r0), "=r"(r1), "=r"(r2), "=r"(r3) : "r"(addr))

#define MMA16816(d, a, b) \
    asm volatile("mma.sync.aligned.m16n8k16.row.col.f32.f16.f16.f32 " \
        "{%0,%1,%2,%3}, {%4,%5,%6,%7}, {%8,%9}, {%0,%1,%2,%3};\n" \
        : "+f"((d)[0]), "+f"((d)[1]), "+f"((d)[2]), "+f"((d)[3]) \
        : "r"((a)[0]), "r"((a)[1]), "r"((a)[2]), "r"((a)[3]), "r"((b)[0]), "r"((b)[1]))

// ---------------- x fp32 -> fp16 ----------------
__global__ void f2h_kernel(const float* __restrict__ x) {
    size_t i = (size_t)blockIdx.x * blockDim.x + threadIdx.x;
    float4 v = ((const float4*)x)[i];
    __half2* o = (__half2*)g_X;
    o[2 * i + 0] = __floats2half2_rn(v.x, v.y);
    o[2 * i + 1] = __floats2half2_rn(v.z, v.w);
}

// ---------------- AWQ int4 dequant -> fp16 row-major [rows, cols] ----------------
template <int WHICH>
__global__ void dequant_kernel(const int* __restrict__ qw, const float* __restrict__ sc,
                               const int* __restrict__ qz, int rows, int cols) {
    __half* W = (WHICH == 0) ? g_Wg : (WHICH == 1) ? g_Wu : g_Wd;
    const int wpr = cols >> 3;
    size_t idx = (size_t)blockIdx.x * blockDim.x + threadIdx.x;
    if (idx >= (size_t)rows * wpr) return;
    int j = (int)(idx % wpr);
    int k = (int)(idx / wpr);
    int grp = k >> 7;

    unsigned w = ((const unsigned*)qw)[idx];
    unsigned z = ((const unsigned*)qz)[(size_t)grp * wpr + j];
    const float* srow = sc + (size_t)grp * cols + j * 8;
    float4 s0 = *(const float4*)(srow);
    float4 s1 = *(const float4*)(srow + 4);

    __half2 h[4];
    h[0] = __floats2half2_rn((float)((int)(w & 0xF)         - (int)(z & 0xF))         * s0.x,
                             (float)((int)((w >> 4) & 0xF)  - (int)((z >> 4) & 0xF))  * s0.y);
    h[1] = __floats2half2_rn((float)((int)((w >> 8) & 0xF)  - (int)((z >> 8) & 0xF))  * s0.z,
                             (float)((int)((w >> 12) & 0xF) - (int)((z >> 12) & 0xF)) * s0.w);
    h[2] = __floats2half2_rn((float)((int)((w >> 16) & 0xF) - (int)((z >> 16) & 0xF)) * s1.x,
                             (float)((int)((w >> 20) & 0xF) - (int)((z >> 20) & 0xF)) * s1.y);
    h[3] = __floats2half2_rn((float)((int)((w >> 24) & 0xF) - (int)((z >> 24) & 0xF)) * s1.z,
                             (float)((int)((w >> 28) & 0xF) - (int)((z >> 28) & 0xF)) * s1.w);

    *(uint4*)(W + (size_t)k * cols + j * 8) = *(uint4*)h;
}

// ============================================================================
// GEMM1 (fused gate+up): BM=256, 64 gate cols + 64 up cols, BK=64 per stage.
// 512 threads = 16 warps = 4(m) x 4(n). Warp: 64 rows x (16 gate + 16 up) cols.
// TMA SW128 layout: tile row r at base + r*128; ldmatrix xor = (lane&7)<<4.
// ============================================================================
constexpr int GU_KT = KK / 64;   // 64

__global__ __launch_bounds__(512, 1) void gemm_gateup(
    const __grid_constant__ CUtensorMap mA,
    const __grid_constant__ CUtensorMap mBg,
    const __grid_constant__ CUtensorMap mBu)
{
    extern __shared__ __align__(1024) char smem[];
    const uint32_t sb = smem_u32(smem);
    const int tid  = threadIdx.x;
    const int lane = tid & 31;
    const int warp = tid >> 5;
    const int wm   = warp & 3;
    const int wn   = warp >> 2;
    const int m0   = blockIdx.x * 256;
    const int n0   = blockIdx.y * 64;

    if (tid == 0) {
        for (int i = 0; i < NS; ++i) {
            MBAR_INIT(sb + i * 16, 1);       // full (tx-based)
            MBAR_INIT(sb + i * 16 + 8, 16);  // empty (one arrive per warp)
        }
    }
    __syncthreads();

#define GU_LOAD(slot, stg) do {                                     \
        uint32_t _d  = sb + 1024 + (uint32_t)(slot) * GU_STAGE;     \
        uint32_t _fb = sb + (slot) * 16;                            \
        int _k0 = (stg) * 64;                                       \
        MBAR_EXPECT_TX(_fb, GU_STAGE);                              \
        TMA2D(_d,         &mA,  _k0, m0, _fb);                      \
        TMA2D(_d + 32768, &mBg, n0,  _k0, _fb);                     \
        TMA2D(_d + 40960, &mBu, n0,  _k0, _fb);                     \
    } while (0)

    if (tid == 0) {
#pragma unroll
        for (int p = 0; p < NS; ++p) GU_LOAD(p, p);
    }

    float cg[4][2][4];
    float cu[4][2][4];
#pragma unroll
    for (int i = 0; i < 4; i++)
#pragma unroll
        for (int j = 0; j < 2; j++)
#pragma unroll
            for (int l = 0; l < 4; l++) { cg[i][j][l] = 0.f; cu[i][j][l] = 0.f; }

    // per-lane address pieces
    const uint32_t xr = (uint32_t)(lane & 7) << 4;        // swizzle xor
    const uint32_t aro = (uint32_t)(wm * 64 + (lane & 15)) * 128;
    const uint32_t acb = (uint32_t)((lane >> 4) << 4);    // 0 or 16 bytes
    const uint32_t bro = (uint32_t)(lane & 15) * 128;
    const uint32_t bcb = (uint32_t)(wn * 32 + ((lane >> 4) << 4));

    for (int s = 0; s < GU_KT; ++s) {
        const int slot = s & (NS - 1);
        const uint32_t par = (uint32_t)((s / NS) & 1);
        MBAR_WAIT(sb + slot * 16, par);

        const uint32_t abase  = sb + 1024 + (uint32_t)slot * GU_STAGE;
        const uint32_t bgbase = abase + 32768;
        const uint32_t bubase = abase + 40960;

#pragma unroll
        for (int ks = 0; ks < 4; ++ks) {
            uint32_t a[4][4];
#pragma unroll
            for (int mi = 0; mi < 4; ++mi) {
                uint32_t addr = abase + aro + (uint32_t)(mi * 16 * 128) +
                                (((uint32_t)(ks * 32) + acb) ^ xr);
                LDSM4(a[mi], addr);
            }
            uint32_t bg[2][2], bu[2][2];
            {
                uint32_t off = bro + (uint32_t)(ks * 16 * 128) + (bcb ^ xr);
                LDSM4T(bg[0][0], bg[0][1], bg[1][0], bg[1][1], bgbase + off);
                LDSM4T(bu[0][0], bu[0][1], bu[1][0], bu[1][1], bubase + off);
            }
#pragma unroll
            for (int mi = 0; mi < 4; ++mi)
#pragma unroll
                for (int nj = 0; nj < 2; ++nj) {
                    MMA16816(cg[mi][nj], a[mi], bg[nj]);
                    MMA16816(cu[mi][nj], a[mi], bu[nj]);
                }
        }

        if (lane == 0) MBAR_ARRIVE(sb + slot * 16 + 8);
        if (tid == 0 && s + NS < GU_KT) {
            MBAR_WAIT_RLX(sb + slot * 16 + 8, par);
            GU_LOAD(slot, s + NS);
        }
    }
#undef GU_LOAD

    // epilogue: h = silu(g) * u (warp-local)
#pragma unroll
    for (int mi = 0; mi < 4; ++mi)
#pragma unroll
        for (int nj = 0; nj < 2; ++nj) {
            int r = m0 + wm * 64 + mi * 16 + (lane >> 2);
            int c = n0 + wn * 16 + nj * 8 + (lane & 3) * 2;
            float g0 = cg[mi][nj][0], g1 = cg[mi][nj][1];
            float g2 = cg[mi][nj][2], g3 = cg[mi][nj][3];
            float u0 = cu[mi][nj][0], u1 = cu[mi][nj][1];
            float u2 = cu[mi][nj][2], u3 = cu[mi][nj][3];
            float h0 = g0 / (1.f + __expf(-g0)) * u0;
            float h1 = g1 / (1.f + __expf(-g1)) * u1;
            float h2 = g2 / (1.f + __expf(-g2)) * u2;
            float h3 = g3 / (1.f + __expf(-g3)) * u3;
            *(__half2*)(g_H + (size_t)r * II + c)       = __floats2half2_rn(h0, h1);
            *(__half2*)(g_H + (size_t)(r + 8) * II + c) = __floats2half2_rn(h2, h3);
        }
}

// ============================================================================
// GEMM2 (down): BM=256, BN=128 (two 64-col B tiles), BK=64 per stage.
// 512 threads = 16 warps = 4(m) x 4(n). Warp tile: 64 x 32.
// ============================================================================
constexpr int DN_KT = II / 64;   // 172

__global__ __launch_bounds__(512, 1) void gemm_down(
    const __grid_constant__ CUtensorMap mA,
    const __grid_constant__ CUtensorMap mB,
    float* __restrict__ out)
{
    extern __shared__ __align__(1024) char smem[];
    const uint32_t sb = smem_u32(smem);
    const int tid  = threadIdx.x;
    const int lane = tid & 31;
    const int warp = tid >> 5;
    const int wm   = warp & 3;
    const int wn   = warp >> 2;
    const int m0   = blockIdx.x * 256;
    const int n0   = blockIdx.y * 128;

    if (tid == 0) {
        for (int i = 0; i < NS; ++i) {
            MBAR_INIT(sb + i * 16, 1);
            MBAR_INIT(sb + i * 16 + 8, 16);
        }
    }
    __syncthreads();

#define DN_LOAD(slot, stg) do {                                     \
        uint32_t _d  = sb + 1024 + (uint32_t)(slot) * DN_STAGE;     \
        uint32_t _fb = sb + (slot) * 16;                            \
        int _k0 = (stg) * 64;                                       \
        MBAR_EXPECT_TX(_fb, DN_STAGE);                              \
        TMA2D(_d,         &mA, _k0, m0,  _fb);                      \
        TMA2D(_d + 32768, &mB, n0,      _k0, _fb);                  \
        TMA2D(_d + 40960, &mB, n0 + 64, _k0, _fb);                  \
    } while (0)

    if (tid == 0) {
#pragma unroll
        for (int p = 0; p < NS; ++p) DN_LOAD(p, p);
    }

    float cc[4][4][4];
#pragma unroll
    for (int i = 0; i < 4; i++)
#pragma unroll
        for (int j = 0; j < 4; j++)
#pragma unroll
            for (int l = 0; l < 4; l++) cc[i][j][l] = 0.f;

    const uint32_t xr = (uint32_t)(lane & 7) << 4;
    const uint32_t aro = (uint32_t)(wm * 64 + (lane & 15)) * 128;
    const uint32_t acb = (uint32_t)((lane >> 4) << 4);
    const uint32_t bro = (uint32_t)(lane & 15) * 128;
    const uint32_t btile = (uint32_t)(wn >> 1) * 8192;     // which 64-col B tile
    const uint32_t bcb = (uint32_t)((wn & 1) * 64 + ((lane >> 4) << 4));

    for (int s = 0; s < DN_KT; ++s) {
        const int slot = s & (NS - 1);
        const uint32_t par = (uint32_t)((s / NS) & 1);
        MBAR_WAIT(sb + slot * 16, par);

        const uint32_t abase = sb + 1024 + (uint32_t)slot * DN_STAGE;
        const uint32_t bbase = abase + 32768 + btile;

#pragma unroll
        for (int ks = 0; ks < 4; ++ks) {
            uint32_t a[4][4];
#pragma unroll
            for (int mi = 0; mi < 4; ++mi) {
                uint32_t addr = abase + aro + (uint32_t)(mi * 16 * 128) +
                                (((uint32_t)(ks * 32) + acb) ^ xr);
                LDSM4(a[mi], addr);
            }
            uint32_t b[4][2];
#pragma unroll
            for (int nh = 0; nh < 2; ++nh) {
                uint32_t addr = bbase + bro + (uint32_t)(ks * 16 * 128) +
                                ((bcb + (uint32_t)(nh * 32)) ^ xr);
                LDSM4T(b[nh * 2][0], b[nh * 2][1], b[nh * 2 + 1][0], b[nh * 2 + 1][1], addr);
            }
#pragma unroll
            for (int mi = 0; mi < 4; ++mi)
#pragma unroll
                for (int nj = 0; nj < 4; ++nj) MMA16816(cc[mi][nj], a[mi], b[nj]);
        }

        if (lane == 0) MBAR_ARRIVE(sb + slot * 16 + 8);
        if (tid == 0 && s + NS < DN_KT) {
            MBAR_WAIT_RLX(sb + slot * 16 + 8, par);
            DN_LOAD(slot, s + NS);
        }
    }
#undef DN_LOAD

#pragma unroll
    for (int mi = 0; mi < 4; ++mi)
#pragma unroll
        for (int nj = 0; nj < 4; ++nj) {
            int r = m0 + wm * 64 + mi * 16 + (lane >> 2);
            int c = n0 + wn * 32 + nj * 8 + (lane & 3) * 2;
            *(float2*)(out + (size_t)r * OO + c)       = make_float2(cc[mi][nj][0], cc[mi][nj][1]);
            *(float2*)(out + (size_t)(r + 8) * OO + c) = make_float2(cc[mi][nj][2], cc[mi][nj][3]);
        }
}

// ---------------- host: tensormap construction ----------------
typedef CUresult (*PFN_encode)(CUtensorMap*, CUtensorMapDataType, cuuint32_t, void*,
                               const cuuint64_t*, const cuuint64_t*, const cuuint32_t*,
                               const cuuint32_t*, CUtensorMapInterleave, CUtensorMapSwizzle,
                               CUtensorMapL2promotion, CUtensorMapFloatOOBfill);

static void make_map(PFN_encode enc, CUtensorMap* m, void* ptr,
                     unsigned long long d0, unsigned long long d1,
                     unsigned b0, unsigned b1) {
    cuuint64_t dims[2] = {d0, d1};
    cuuint64_t strides[1] = {d0 * 2};  // fp16 bytes
    cuuint32_t box[2] = {b0, b1};
    cuuint32_t es[2] = {1, 1};
    enc(m, CU_TENSOR_MAP_DATA_TYPE_FLOAT16, 2, ptr, dims, strides, box, es,
        CU_TENSOR_MAP_INTERLEAVE_NONE, CU_TENSOR_MAP_SWIZZLE_128B,
        CU_TENSOR_MAP_L2_PROMOTION_L2_128B, CU_TENSOR_MAP_FLOAT_OOB_FILL_NONE);
}

extern "C" void kernel_launch(void* const* d_in, const int* in_sizes, int n_in,
                              void* d_out, int out_size) {
    (void)in_sizes; (void)n_in; (void)out_size;
    const float* x   = (const float*)d_in[0];
    const int*   gqw = (const int*)d_in[1];
    const float* gsc = (const float*)d_in[2];
    const int*   gqz = (const int*)d_in[3];
    const int*   uqw = (const int*)d_in[4];
    const float* usc = (const float*)d_in[5];
    const int*   uqz = (const int*)d_in[6];
    const int*   dqw = (const int*)d_in[7];
    const float* dsc = (const float*)d_in[8];
    const int*   dqz = (const int*)d_in[9];
    float* out = (float*)d_out;

    PFN_encode enc = nullptr;
    cudaDriverEntryPointQueryResult qr;
    cudaGetDriverEntryPointByVersion("cuTensorMapEncodeTiled", (void**)&enc, 12000,
                                     cudaEnableDefault, &qr);
    void *pX, *pWg, *pWu, *pWd, *pH;
    cudaGetSymbolAddress(&pX,  g_X);
    cudaGetSymbolAddress(&pWg, g_Wg);
    cudaGetSymbolAddress(&pWu, g_Wu);
    cudaGetSymbolAddress(&pWd, g_Wd);
    cudaGetSymbolAddress(&pH,  g_H);

    static CUtensorMap mX, mWg, mWu, mWd, mH;
    make_map(enc, &mX,  pX,  KK, TT, 64, 256);  // A1: X [T,K]
    make_map(enc, &mWg, pWg, II, KK, 64, 64);   // Bg: Wg [K,I]
    make_map(enc, &mWu, pWu, II, KK, 64, 64);   // Bu
    make_map(enc, &mH,  pH,  II, TT, 64, 256);  // A2: H [T,I]
    make_map(enc, &mWd, pWd, OO, II, 64, 64);   // Bd: Wd [I,O]

    // x -> fp16
    f2h_kernel<<<(TT * KK / 4) / 256, 256>>>(x);

    // dequant weights
    int words1 = KK * (II / 8);
    dequant_kernel<0><<<(words1 + 255) / 256, 256>>>(gqw, gsc, gqz, KK, II);
    dequant_kernel<1><<<(words1 + 255) / 256, 256>>>(uqw, usc, uqz, KK, II);
    int words2 = II * (OO / 8);
    dequant_kernel<2><<<(words2 + 255) / 256, 256>>>(dqw, dsc, dqz, II, OO);

    // fused gate/up GEMM + silu*mul (TMA-fed)
    cudaFuncSetAttribute(gemm_gateup, cudaFuncAttributeMaxDynamicSharedMemorySize, SMEM_BYTES);
    gemm_gateup<<<dim3(TT / 256, II / 64), 512, SMEM_BYTES>>>(mX, mWg, mWu);

    // down GEMM (TMA-fed)
    cudaFuncSetAttribute(gemm_down, cudaFuncAttributeMaxDynamicSharedMemorySize, SMEM_BYTES);
    gemm_down<<<dim3(TT / 256, OO / 128), 512, SMEM_BYTES>>>(mH, mWd, out);
}